// round 3
// baseline (speedup 1.0000x reference)
#include <cuda_runtime.h>
#include <cuda_bf16.h>
#include <cstdint>

// Problem shape (fixed by dataset: X is [8192, 64] fp32)
#define NROWS 8192
#define DDIM  64

// -------- device scratch (static allocation only) ---------------------------
__device__ float g_sq[NROWS];        // per-row ||x||^2 (fp32, exact)
__device__ float g_cp[64 * DDIM];    // partial column sums (64 blocks x 64 cols)
__device__ float g_invl;             // log2(e) / (2*sigma^2)

// ------------------------- kernel 1: per-row ||x||^2 ------------------------
__global__ void gk_sq(const float* __restrict__ X) {
    int gtid = blockIdx.x * blockDim.x + threadIdx.x;
    int w = gtid >> 5;                 // one warp per row
    int lane = threadIdx.x & 31;
    const float* row = X + (size_t)w * DDIM;
    float a = row[lane], b = row[lane + 32];
    float p = a * a + b * b;
    #pragma unroll
    for (int o = 16; o > 0; o >>= 1)
        p += __shfl_xor_sync(0xffffffffu, p, o);
    if (lane == 0) g_sq[w] = p;
}

// --------------- kernel 2: partial column sums (for mean vector) ------------
__global__ void gk_colpart(const float* __restrict__ X) {
    __shared__ float scs[1024];
    int t = threadIdx.x;
    int col = t & 63, stripe = t >> 6;         // 16 stripes x 8 rows
    int base = blockIdx.x * 128 + stripe * 8;
    float s = 0.f;
    #pragma unroll
    for (int r = 0; r < 8; r++)
        s += X[(size_t)(base + r) * DDIM + col];
    scs[t] = s;
    __syncthreads();
    if (t < 64) {
        float c = 0.f;
        #pragma unroll
        for (int st = 0; st < 16; st++) c += scs[st * 64 + t];
        g_cp[blockIdx.x * 64 + t] = c;
    }
}

// --------------- kernel 3: finish stats -> log2e/(2 sigma^2) ----------------
// mean(d2) = 2*mean(sq) - 2*||mu||^2 (clamp correction is O(1e-9) relative)
__global__ void gk_finish(int n) {
    __shared__ float ssq[1024];
    __shared__ float smu[64];
    int t = threadIdx.x;
    float q = 0.f;
    for (int r = t; r < n; r += 1024) q += g_sq[r];
    ssq[t] = q;
    __syncthreads();
    for (int sft = 512; sft > 0; sft >>= 1) {
        if (t < sft) ssq[t] += ssq[t + sft];
        __syncthreads();
    }
    if (t < 64) {
        float c = 0.f;
        #pragma unroll
        for (int b = 0; b < 64; b++) c += g_cp[b * 64 + t];
        smu[t] = c / (float)n;                 // mu_k
    }
    __syncthreads();
    if (t == 0) {
        float mu2 = 0.f;
        #pragma unroll
        for (int k = 0; k < 64; k++) mu2 += smu[k] * smu[k];
        float meansq = ssq[0] / (float)n;
        float meand2 = 2.f * meansq - 2.f * mu2;   // ALPHA = 1
        g_invl = 1.44269504f / (2.f * meand2);     // log2(e)/(2 sigma^2)
    }
}

// ------------------------- kernel 4: main tile kernel ------------------------
// CTA: 128x128 output tile via tf32 mma.sync.m16n8k8, register accumulators.
// 8 warps laid out 4(m) x 2(n); warp tile 32x64.
// SMEM layout uses k-permutation pos(k) = 8*(k>>3) + 2*(k&3) + ((k>>2)&1)
// so each thread's (k, k+4) fragment pair is ADJACENT -> LDS.64.
// Row stride 72 floats (72 mod 32 = 8) -> provably conflict-free LDS.64/STS.128.
#define BM 128
#define BN 128
#define SSTRIDE 72   // floats

static constexpr int SMEM_FLOATS = 2 * BM * SSTRIDE + 256;
static constexpr int SMEM_BYTES  = SMEM_FLOATS * 4;   // 74752

__device__ __forceinline__ uint32_t f2tf32(float x) {
    uint32_t r;
    asm("cvt.rna.tf32.f32 %0, %1;" : "=r"(r) : "f"(x));
    return r;
}

__device__ __forceinline__ void mma_tf32(float* c, const uint32_t* a, const uint32_t* b) {
    asm volatile(
        "mma.sync.aligned.m16n8k8.row.col.f32.tf32.tf32.f32 "
        "{%0,%1,%2,%3}, {%4,%5,%6,%7}, {%8,%9}, {%0,%1,%2,%3};"
        : "+f"(c[0]), "+f"(c[1]), "+f"(c[2]), "+f"(c[3])
        : "r"(a[0]), "r"(a[1]), "r"(a[2]), "r"(a[3]), "r"(b[0]), "r"(b[1]));
}

__device__ __forceinline__ float gauss_elem(float acc, float sj, float nsqi, float invl) {
    float u = fmaf(2.f, acc, nsqi - sj);   // u = 2*dot - sq_i - sq_j = -d2
    float a = fminf(u * invl, 0.f);        // = -max(d2,0)*log2e/(2 sigma^2)
    float r;
    asm("ex2.approx.f32 %0, %1;" : "=f"(r) : "f"(a));
    return r;
}

__global__ void __launch_bounds__(256, 2)
gk_main(const float* __restrict__ X, float* __restrict__ out, int n) {
    extern __shared__ float smem[];
    float* As  = smem;                          // [128][72] tf32 bits, k-permuted
    float* Bs  = smem + BM * SSTRIDE;           // [128][72]
    float* sqi = smem + 2 * BM * SSTRIDE;       // [128]
    float* sqj = sqi + 128;                     // [128]

    int tid = threadIdx.x;
    int bi = blockIdx.y, bj = blockIdx.x;

    // ---- cooperative load: fp32 -> tf32 bits, k-permuted, conflict-free ----
    // Per thread: 16 units (8 A-rows' halves + 8 B). Unit = (row, kk, s):
    //   reads k = 8kk+2s..+1 and 8kk+2s+4..+5, writes STS.128 at row*72+8kk+4s
    //   in pos order (x0, x0+4, x1, x1+4).
    {
        int lane = tid & 31, warp = tid >> 5;
        int r2 = lane >> 4;            // 0..1
        int kk = (lane >> 1) & 7;      // 0..7
        int s  = lane & 1;             // 0..1
        const float* gA = X + (size_t)bi * BM * DDIM;
        const float* gB = X + (size_t)bj * BN * DDIM;
        #pragma unroll
        for (int c = 0; c < 8; c++) {
            int row = c * 16 + warp * 2 + r2;
            const float* srcA = gA + row * DDIM + kk * 8 + 2 * s;
            const float* srcB = gB + row * DDIM + kk * 8 + 2 * s;
            float2 ua = *reinterpret_cast<const float2*>(srcA);
            float2 va = *reinterpret_cast<const float2*>(srcA + 4);
            float2 ub = *reinterpret_cast<const float2*>(srcB);
            float2 vb = *reinterpret_cast<const float2*>(srcB + 4);
            uint4 wa, wb;
            wa.x = f2tf32(ua.x); wa.y = f2tf32(va.x);
            wa.z = f2tf32(ua.y); wa.w = f2tf32(va.y);
            wb.x = f2tf32(ub.x); wb.y = f2tf32(vb.x);
            wb.z = f2tf32(ub.y); wb.w = f2tf32(vb.y);
            int off = row * SSTRIDE + kk * 8 + 4 * s;
            *reinterpret_cast<uint4*>(&As[off]) = wa;
            *reinterpret_cast<uint4*>(&Bs[off]) = wb;
        }
        if (tid < 128) sqi[tid] = g_sq[bi * BM + tid];
        else           sqj[tid - 128] = g_sq[bj * BN + (tid - 128)];
    }
    __syncthreads();

    // ---- warp-level tf32 GEMM ----------------------------------------------
    int wid = tid >> 5, lane = tid & 31;
    int wm = wid & 3, wn = wid >> 2;            // 4 x 2 warp grid
    int gq = lane >> 2, q4 = lane & 3;          // group / quad-thread

    float acc[2][8][4];
    #pragma unroll
    for (int mt = 0; mt < 2; mt++)
        #pragma unroll
        for (int nt = 0; nt < 8; nt++)
            #pragma unroll
            for (int r = 0; r < 4; r++) acc[mt][nt][r] = 0.f;

    #pragma unroll
    for (int kk = 0; kk < 8; kk++) {
        int kbase = kk * 8 + 2 * q4;           // permuted pos of (k0, k0+4)
        // A fragments: (a0,a2) from row, (a1,a3) from row+8 — one LDS.64 each
        uint32_t afr[2][4];
        #pragma unroll
        for (int mt = 0; mt < 2; mt++) {
            int row = wm * 32 + mt * 16 + gq;
            float2 lo = *reinterpret_cast<const float2*>(&As[row * SSTRIDE + kbase]);
            float2 hi = *reinterpret_cast<const float2*>(&As[(row + 8) * SSTRIDE + kbase]);
            afr[mt][0] = __float_as_uint(lo.x);
            afr[mt][1] = __float_as_uint(hi.x);
            afr[mt][2] = __float_as_uint(lo.y);
            afr[mt][3] = __float_as_uint(hi.y);
        }
        uint32_t bfr[8][2];
        #pragma unroll
        for (int nt = 0; nt < 8; nt++) {
            int col = wn * 64 + nt * 8 + gq;
            float2 b = *reinterpret_cast<const float2*>(&Bs[col * SSTRIDE + kbase]);
            bfr[nt][0] = __float_as_uint(b.x);
            bfr[nt][1] = __float_as_uint(b.y);
        }
        #pragma unroll
        for (int mt = 0; mt < 2; mt++)
            #pragma unroll
            for (int nt = 0; nt < 8; nt++)
                mma_tf32(acc[mt][nt], afr[mt], bfr[nt]);
    }

    // ---- fused epilogue: exp(-max(d2,0)/(2 sigma^2)), direct STG -----------
    float invl = g_invl;
    #pragma unroll
    for (int mt = 0; mt < 2; mt++) {
        #pragma unroll
        for (int rr = 0; rr < 2; rr++) {
            int rloc = wm * 32 + mt * 16 + gq + rr * 8;
            int grow = bi * BM + rloc;
            float nsqi = -sqi[rloc];
            float* orow = out + (size_t)grow * n + bj * BN;
            #pragma unroll
            for (int nt = 0; nt < 8; nt++) {
                int c0 = wn * 64 + nt * 8 + 2 * q4;
                float2 v;
                v.x = gauss_elem(acc[mt][nt][rr * 2 + 0], sqj[c0],     nsqi, invl);
                v.y = gauss_elem(acc[mt][nt][rr * 2 + 1], sqj[c0 + 1], nsqi, invl);
                *reinterpret_cast<float2*>(orow + c0) = v;
            }
        }
    }
}

// ------------------------------ launch ---------------------------------------
extern "C" void kernel_launch(void* const* d_in, const int* in_sizes, int n_in,
                              void* d_out, int out_size) {
    const float* X = (const float*)d_in[0];
    int n = in_sizes[0] / DDIM;          // 8192
    float* out = (float*)d_out;

    cudaFuncSetAttribute(gk_main, cudaFuncAttributeMaxDynamicSharedMemorySize,
                         SMEM_BYTES);

    gk_sq<<<n / 8, 256>>>(X);            // 1024 CTAs, one warp per row
    gk_colpart<<<64, 1024>>>(X);
    gk_finish<<<1, 1024>>>(n);
    dim3 grid(n / BN, n / BM);
    gk_main<<<grid, 256, SMEM_BYTES>>>(X, out, n);
}

// round 4
// speedup vs baseline: 1.2529x; 1.2529x over previous
#include <cuda_runtime.h>
#include <cuda_bf16.h>
#include <cstdint>

// Problem shape (fixed by dataset: X is [8192, 64] fp32)
#define NROWS 8192
#define DDIM  64

// -------- device scratch (static allocation only) ---------------------------
__device__ float g_sq[NROWS];        // per-row ||x||^2 (fp32, exact)
__device__ float g_cp[64 * DDIM];    // partial column sums (64 blocks x 64 cols)
__device__ float g_invl;             // log2(e) / (2*sigma^2)

// ------------------------- kernel 1: per-row ||x||^2 ------------------------
__global__ void gk_sq(const float* __restrict__ X) {
    int gtid = blockIdx.x * blockDim.x + threadIdx.x;
    int w = gtid >> 5;                 // one warp per row
    int lane = threadIdx.x & 31;
    const float* row = X + (size_t)w * DDIM;
    float a = row[lane], b = row[lane + 32];
    float p = a * a + b * b;
    #pragma unroll
    for (int o = 16; o > 0; o >>= 1)
        p += __shfl_xor_sync(0xffffffffu, p, o);
    if (lane == 0) g_sq[w] = p;
}

// --------------- kernel 2: partial column sums (for mean vector) ------------
__global__ void gk_colpart(const float* __restrict__ X) {
    __shared__ float scs[1024];
    int t = threadIdx.x;
    int col = t & 63, stripe = t >> 6;         // 16 stripes x 8 rows
    int base = blockIdx.x * 128 + stripe * 8;
    float s = 0.f;
    #pragma unroll
    for (int r = 0; r < 8; r++)
        s += X[(size_t)(base + r) * DDIM + col];
    scs[t] = s;
    __syncthreads();
    if (t < 64) {
        float c = 0.f;
        #pragma unroll
        for (int st = 0; st < 16; st++) c += scs[st * 64 + t];
        g_cp[blockIdx.x * 64 + t] = c;
    }
}

// --------------- kernel 3: finish stats -> log2e/(2 sigma^2) ----------------
// mean(d2) = 2*mean(sq) - 2*||mu||^2 (clamp correction is O(1e-9) relative)
__global__ void gk_finish(int n) {
    __shared__ float ssq[1024];
    __shared__ float smu[64];
    int t = threadIdx.x;
    float q = 0.f;
    for (int r = t; r < n; r += 1024) q += g_sq[r];
    ssq[t] = q;
    __syncthreads();
    for (int sft = 512; sft > 0; sft >>= 1) {
        if (t < sft) ssq[t] += ssq[t + sft];
        __syncthreads();
    }
    if (t < 64) {
        float c = 0.f;
        #pragma unroll
        for (int b = 0; b < 64; b++) c += g_cp[b * 64 + t];
        smu[t] = c / (float)n;                 // mu_k
    }
    __syncthreads();
    if (t == 0) {
        float mu2 = 0.f;
        #pragma unroll
        for (int k = 0; k < 64; k++) mu2 += smu[k] * smu[k];
        float meansq = ssq[0] / (float)n;
        float meand2 = 2.f * meansq - 2.f * mu2;   // ALPHA = 1
        g_invl = 1.44269504f / (2.f * meand2);     // log2(e)/(2 sigma^2)
    }
}

// ------------------------- kernel 4: main tile kernel ------------------------
// Triangular grid (bi <= bj): each CTA computes its 128x128 tile once,
// writes it directly, then writes the transposed mirror tile via SMEM
// staging with fully coalesced STG.128.
// GEMM: tf32 mma.sync.m16n8k8, 8 warps 4(m) x 2(n), warp tile 32x64.
#define BM 128
#define BN 128
#define SA_STRIDE 68    // operand tiles (R2 layout, proven)
#define TSTRIDE   132   // transpose staging stride: bank = (8*q4+gq) all-distinct

#define NTILE 64        // 8192 / 128
#define NTRI  (NTILE * (NTILE + 1) / 2)   // 2080

static constexpr int SMEM_FLOATS = 2 * BM * SA_STRIDE + 256;  // 17664
static constexpr int SMEM_BYTES  = SMEM_FLOATS * 4;           // 70656
// staging T = 128 * 132 = 16896 floats (fits inside the 2*128*68 operand area)

__device__ __forceinline__ uint32_t f2tf32(float x) {
    uint32_t r;
    asm("cvt.rna.tf32.f32 %0, %1;" : "=r"(r) : "f"(x));
    return r;
}

__device__ __forceinline__ void mma_tf32(float* c, const uint32_t* a, const uint32_t* b) {
    asm volatile(
        "mma.sync.aligned.m16n8k8.row.col.f32.tf32.tf32.f32 "
        "{%0,%1,%2,%3}, {%4,%5,%6,%7}, {%8,%9}, {%0,%1,%2,%3};"
        : "+f"(c[0]), "+f"(c[1]), "+f"(c[2]), "+f"(c[3])
        : "r"(a[0]), "r"(a[1]), "r"(a[2]), "r"(a[3]), "r"(b[0]), "r"(b[1]));
}

__device__ __forceinline__ float gauss_elem(float acc, float sj, float nsqi, float invl) {
    float u = fmaf(2.f, acc, nsqi - sj);   // u = 2*dot - sq_i - sq_j = -d2
    float a = fminf(u * invl, 0.f);        // = -max(d2,0)*log2e/(2 sigma^2)
    float r;
    asm("ex2.approx.f32 %0, %1;" : "=f"(r) : "f"(a));
    return r;
}

// Start index of triangle row bi: Start(bi) = bi*(2*NTILE+1-bi)/2
__device__ __forceinline__ int tri_start(int bi) {
    return (bi * (2 * NTILE + 1 - bi)) >> 1;
}

__global__ void __launch_bounds__(256, 2)
gk_main(const float* __restrict__ X, float* __restrict__ out, int n) {
    extern __shared__ float smem[];
    float* As  = smem;                          // [128][68] tf32 bits
    float* Bs  = smem + BM * SA_STRIDE;         // [128][68]
    float* sqi = smem + 2 * BM * SA_STRIDE;     // [128]
    float* sqj = sqi + 128;                     // [128]
    float* T   = smem;                          // staging, reused after barrier

    int tid = threadIdx.x;

    // ---- decode triangular block index: bi <= bj ---------------------------
    int t = blockIdx.x;
    int bi = (int)((129.0f - sqrtf(16641.0f - 8.0f * (float)t)) * 0.5f);
    if (bi < 0) bi = 0;
    if (bi > NTILE - 1) bi = NTILE - 1;
    while (bi + 1 <= NTILE - 1 && tri_start(bi + 1) <= t) bi++;
    while (tri_start(bi) > t) bi--;
    int bj = bi + (t - tri_start(bi));

    // ---- cooperative load: global fp32 -> tf32-rounded bits in SMEM --------
    {
        const float4* gA = reinterpret_cast<const float4*>(X + (size_t)bi * BM * DDIM);
        const float4* gB = reinterpret_cast<const float4*>(X + (size_t)bj * BN * DDIM);
        #pragma unroll
        for (int c = 0; c < 8; c++) {
            int e = tid + 256 * c;              // 2048 float4 per tile
            int row = e >> 4, q = e & 15;
            float4 va = gA[e];
            float4 vb = gB[e];
            uint32_t* da = reinterpret_cast<uint32_t*>(&As[row * SA_STRIDE + q * 4]);
            uint32_t* db = reinterpret_cast<uint32_t*>(&Bs[row * SA_STRIDE + q * 4]);
            da[0] = f2tf32(va.x); da[1] = f2tf32(va.y);
            da[2] = f2tf32(va.z); da[3] = f2tf32(va.w);
            db[0] = f2tf32(vb.x); db[1] = f2tf32(vb.y);
            db[2] = f2tf32(vb.z); db[3] = f2tf32(vb.w);
        }
        if (tid < 128) sqi[tid] = g_sq[bi * BM + tid];
        else           sqj[tid - 128] = g_sq[bj * BN + (tid - 128)];
    }
    __syncthreads();

    // ---- warp-level tf32 GEMM ----------------------------------------------
    int wid = tid >> 5, lane = tid & 31;
    int wm = wid & 3, wn = wid >> 2;            // 4 x 2 warp grid
    int gq = lane >> 2, q4 = lane & 3;          // group / quad-thread

    float acc[2][8][4];
    #pragma unroll
    for (int mt = 0; mt < 2; mt++)
        #pragma unroll
        for (int nt = 0; nt < 8; nt++)
            #pragma unroll
            for (int r = 0; r < 4; r++) acc[mt][nt][r] = 0.f;

    const uint32_t* Au = reinterpret_cast<const uint32_t*>(As);
    const uint32_t* Bu = reinterpret_cast<const uint32_t*>(Bs);

    #pragma unroll
    for (int kk = 0; kk < 8; kk++) {
        int k0 = kk * 8 + q4;
        uint32_t afr[2][4];
        #pragma unroll
        for (int mt = 0; mt < 2; mt++) {
            int row = wm * 32 + mt * 16 + gq;
            afr[mt][0] = Au[row * SA_STRIDE + k0];
            afr[mt][1] = Au[(row + 8) * SA_STRIDE + k0];
            afr[mt][2] = Au[row * SA_STRIDE + k0 + 4];
            afr[mt][3] = Au[(row + 8) * SA_STRIDE + k0 + 4];
        }
        uint32_t bfr[8][2];
        #pragma unroll
        for (int nt = 0; nt < 8; nt++) {
            int col = wn * 64 + nt * 8 + gq;
            bfr[nt][0] = Bu[col * SA_STRIDE + k0];
            bfr[nt][1] = Bu[col * SA_STRIDE + k0 + 4];
        }
        #pragma unroll
        for (int mt = 0; mt < 2; mt++)
            #pragma unroll
            for (int nt = 0; nt < 8; nt++)
                mma_tf32(acc[mt][nt], afr[mt], bfr[nt]);
    }

    // ---- epilogue: transform acc in place, direct STG of primary tile ------
    float invl = g_invl;
    #pragma unroll
    for (int mt = 0; mt < 2; mt++) {
        #pragma unroll
        for (int rr = 0; rr < 2; rr++) {
            int rloc = wm * 32 + mt * 16 + gq + rr * 8;
            int grow = bi * BM + rloc;
            float nsqi = -sqi[rloc];
            float* orow = out + (size_t)grow * n + bj * BN;
            #pragma unroll
            for (int nt = 0; nt < 8; nt++) {
                int c0 = wn * 64 + nt * 8 + 2 * q4;
                float2 v;
                v.x = gauss_elem(acc[mt][nt][rr * 2 + 0], sqj[c0],     nsqi, invl);
                v.y = gauss_elem(acc[mt][nt][rr * 2 + 1], sqj[c0 + 1], nsqi, invl);
                acc[mt][nt][rr * 2 + 0] = v.x;     // keep for mirror
                acc[mt][nt][rr * 2 + 1] = v.y;
                *reinterpret_cast<float2*>(orow + c0) = v;
            }
        }
    }

    // ---- mirror tile: transpose through SMEM, coalesced STG ---------------
    if (bi != bj) {
        __syncthreads();   // all warps done with As/Bs/sqi/sqj -> reuse as T
        // STS.32 transposed: T[c][r] = v(r, c); bank = (8*q4 + gq + const),
        // all 32 distinct per instruction.
        #pragma unroll
        for (int mt = 0; mt < 2; mt++) {
            #pragma unroll
            for (int rr = 0; rr < 2; rr++) {
                int rloc = wm * 32 + mt * 16 + gq + rr * 8;
                #pragma unroll
                for (int nt = 0; nt < 8; nt++) {
                    int c0 = wn * 64 + nt * 8 + 2 * q4;
                    T[(c0    ) * TSTRIDE + rloc] = acc[mt][nt][rr * 2 + 0];
                    T[(c0 + 1) * TSTRIDE + rloc] = acc[mt][nt][rr * 2 + 1];
                }
            }
        }
        __syncthreads();
        // Coalesced read + store: warp w handles rows (iter*8 + w) of the
        // transposed tile; 32 lanes x float4 = 512B contiguous per STG.
        #pragma unroll
        for (int iter = 0; iter < 16; iter++) {
            int r = iter * 8 + wid;            // transposed-tile row = global col block row
            float4 v = *reinterpret_cast<const float4*>(&T[r * TSTRIDE + 4 * lane]);
            float* orow = out + (size_t)(bj * BN + r) * n + bi * BM + 4 * lane;
            *reinterpret_cast<float4*>(orow) = v;
        }
    }
}

// ------------------------------ launch ---------------------------------------
extern "C" void kernel_launch(void* const* d_in, const int* in_sizes, int n_in,
                              void* d_out, int out_size) {
    const float* X = (const float*)d_in[0];
    int n = in_sizes[0] / DDIM;          // 8192
    float* out = (float*)d_out;

    cudaFuncSetAttribute(gk_main, cudaFuncAttributeMaxDynamicSharedMemorySize,
                         SMEM_BYTES);

    gk_sq<<<n / 8, 256>>>(X);            // 1024 CTAs, one warp per row
    gk_colpart<<<64, 1024>>>(X);
    gk_finish<<<1, 1024>>>(n);
    gk_main<<<NTRI, 256, SMEM_BYTES>>>(X, out, n);
}

// round 8
// speedup vs baseline: 1.3945x; 1.1130x over previous
#include <cuda_runtime.h>
#include <cuda_bf16.h>
#include <cstdint>

// Problem shape (fixed by dataset: X is [8192, 64] fp32)
#define NROWS 8192
#define DDIM  64

// -------- device scratch (static allocation only) ---------------------------
__device__ float g_sq[NROWS];        // per-row ||x||^2 (fp32, exact)
__device__ float g_cp[64 * DDIM];    // partial column sums (64 blocks x 64 cols)
__device__ float g_invl;             // log2(e) / (2*sigma^2)

// ---------- kernel 1 (fused): per-row ||x||^2 + partial column sums ---------
// 64 blocks x 1024 threads; block handles 128 rows (32 KB chunk, 2nd pass L1-hot)
__global__ void gk_pre(const float* __restrict__ X) {
    __shared__ float scs[1024];
    int t = threadIdx.x;

    // Phase A: row squared norms. 8 threads per row, 8 floats each.
    {
        int row = blockIdx.x * 128 + (t >> 3);
        int sub = t & 7;
        const float4* p = reinterpret_cast<const float4*>(X + (size_t)row * DDIM + sub * 8);
        float4 a = p[0], b = p[1];
        float s = a.x * a.x + a.y * a.y + a.z * a.z + a.w * a.w
                + b.x * b.x + b.y * b.y + b.z * b.z + b.w * b.w;
        s += __shfl_xor_sync(0xffffffffu, s, 1);
        s += __shfl_xor_sync(0xffffffffu, s, 2);
        s += __shfl_xor_sync(0xffffffffu, s, 4);
        if (sub == 0) g_sq[row] = s;
    }

    // Phase B: partial column sums for the mean vector.
    {
        int col = t & 63, stripe = t >> 6;     // 16 stripes x 8 rows
        int base = blockIdx.x * 128 + stripe * 8;
        float s = 0.f;
        #pragma unroll
        for (int r = 0; r < 8; r++)
            s += X[(size_t)(base + r) * DDIM + col];
        scs[t] = s;
        __syncthreads();
        if (t < 64) {
            float c = 0.f;
            #pragma unroll
            for (int st = 0; st < 16; st++) c += scs[st * 64 + t];
            g_cp[blockIdx.x * 64 + t] = c;
        }
    }
}

// --------------- kernel 2: finish stats -> log2e/(2 sigma^2) ----------------
// mean(d2) = 2*mean(sq) - 2*||mu||^2 (clamp correction is O(1e-9) relative)
__global__ void gk_finish(int n) {
    __shared__ float ssq[1024];
    __shared__ float smu[64];
    int t = threadIdx.x;
    float q = 0.f;
    for (int r = t; r < n; r += 1024) q += g_sq[r];
    ssq[t] = q;
    __syncthreads();
    for (int sft = 512; sft > 0; sft >>= 1) {
        if (t < sft) ssq[t] += ssq[t + sft];
        __syncthreads();
    }
    if (t < 64) {
        float c = 0.f;
        #pragma unroll
        for (int b = 0; b < 64; b++) c += g_cp[b * 64 + t];
        smu[t] = c / (float)n;                 // mu_k
    }
    __syncthreads();
    if (t == 0) {
        float mu2 = 0.f;
        #pragma unroll
        for (int k = 0; k < 64; k++) mu2 += smu[k] * smu[k];
        float meansq = ssq[0] / (float)n;
        float meand2 = 2.f * meansq - 2.f * mu2;   // ALPHA = 1
        g_invl = 1.44269504f / (2.f * meand2);     // log2(e)/(2 sigma^2)
    }
}

// ------------------------- kernel 3: main tile kernel ------------------------
// Triangular grid (bi <= bj); 128x128 tile; bf16 mma.sync.m16n8k16 single pass.
// Operand tiles: bf16 [128][72] (stride 72 bf16 = 36 words ≡ 4 mod 32 ->
// conflict-free fragment LDS.32 and writer STS.128 by construction).
// Mirror tile via fp32 SMEM transpose staging (stride 132), coalesced STG.128.
#define BM 128
#define BN 128
#define SBH 72          // bf16 per row in operand tiles (144 bytes)
#define TSTRIDE 132     // fp32 transpose staging stride

#define NTILE 64        // 8192 / 128
#define NTRI  (NTILE * (NTILE + 1) / 2)   // 2080

// Layout: As [128][72] bf16 @0 (18432B), Bs @18432, sqi @36864, sqj @37376.
// Staging T [128][132] fp32 @0 (67584B) reused after barrier.
static constexpr int OFF_BS  = BM * SBH * 2;          // 18432
static constexpr int OFF_SQI = 2 * BM * SBH * 2;      // 36864
static constexpr int OFF_SQJ = OFF_SQI + 512;
static constexpr int SMEM_BYTES = BM * TSTRIDE * 4;   // 67584

__device__ __forceinline__ void mma_bf16(float* c, const uint32_t* a, const uint32_t* b) {
    asm volatile(
        "mma.sync.aligned.m16n8k16.row.col.f32.bf16.bf16.f32 "
        "{%0,%1,%2,%3}, {%4,%5,%6,%7}, {%8,%9}, {%0,%1,%2,%3};"
        : "+f"(c[0]), "+f"(c[1]), "+f"(c[2]), "+f"(c[3])
        : "r"(a[0]), "r"(a[1]), "r"(a[2]), "r"(a[3]), "r"(b[0]), "r"(b[1]));
}

__device__ __forceinline__ float gauss_elem(float acc, float sj, float nsqi, float invl) {
    float u = fmaf(2.f, acc, nsqi - sj);   // u = 2*dot - sq_i - sq_j = -d2
    float a = fminf(u * invl, 0.f);        // = -max(d2,0)*log2e/(2 sigma^2)
    float r;
    asm("ex2.approx.f32 %0, %1;" : "=f"(r) : "f"(a));
    return r;
}

// Start index of triangle row bi: Start(bi) = bi*(2*NTILE+1-bi)/2
__device__ __forceinline__ int tri_start(int bi) {
    return (bi * (2 * NTILE + 1 - bi)) >> 1;
}

__device__ __forceinline__ uint32_t pack_bf16x2(float lo, float hi) {
    __nv_bfloat162 h = __floats2bfloat162_rn(lo, hi);   // x=lo (low half), y=hi
    return *reinterpret_cast<uint32_t*>(&h);
}

__global__ void __launch_bounds__(256, 2)
gk_main(const float* __restrict__ X, float* __restrict__ out, int n) {
    extern __shared__ unsigned char smem[];
    unsigned char* Asb = smem;                 // bf16 [128][72]
    unsigned char* Bsb = smem + OFF_BS;        // bf16 [128][72]
    float* sqi = reinterpret_cast<float*>(smem + OFF_SQI);   // [128]
    float* sqj = reinterpret_cast<float*>(smem + OFF_SQJ);   // [128]
    float* T   = reinterpret_cast<float*>(smem);             // staging (reused)

    int tid = threadIdx.x;

    // ---- decode triangular block index: bi <= bj ---------------------------
    int t = blockIdx.x;
    int bi = (int)((129.0f - sqrtf(16641.0f - 8.0f * (float)t)) * 0.5f);
    if (bi < 0) bi = 0;
    if (bi > NTILE - 1) bi = NTILE - 1;
    while (bi + 1 <= NTILE - 1 && tri_start(bi + 1) <= t) bi++;
    while (tri_start(bi) > t) bi--;
    int bj = bi + (t - tri_start(bi));

    // ---- cooperative load: fp32 -> bf16 tiles (conflict-free STS.128) ------
    // 1024 16B-units per tile: unit e -> row = e>>3, u = e&7 (k = 8u..8u+7).
    {
        const float* gA = X + (size_t)bi * BM * DDIM;
        const float* gB = X + (size_t)bj * BN * DDIM;
        #pragma unroll
        for (int it = 0; it < 4; it++) {
            int e = tid + 256 * it;
            int row = e >> 3, u = e & 7;
            const float4* pa = reinterpret_cast<const float4*>(gA + row * DDIM + u * 8);
            const float4* pb = reinterpret_cast<const float4*>(gB + row * DDIM + u * 8);
            float4 a0 = pa[0], a1 = pa[1];
            float4 b0 = pb[0], b1 = pb[1];
            uint4 wa, wb;
            wa.x = pack_bf16x2(a0.x, a0.y); wa.y = pack_bf16x2(a0.z, a0.w);
            wa.z = pack_bf16x2(a1.x, a1.y); wa.w = pack_bf16x2(a1.z, a1.w);
            wb.x = pack_bf16x2(b0.x, b0.y); wb.y = pack_bf16x2(b0.z, b0.w);
            wb.z = pack_bf16x2(b1.x, b1.y); wb.w = pack_bf16x2(b1.z, b1.w);
            int off = row * (SBH * 2) + u * 16;
            *reinterpret_cast<uint4*>(Asb + off) = wa;
            *reinterpret_cast<uint4*>(Bsb + off) = wb;
        }
        if (tid < 128) sqi[tid] = g_sq[bi * BM + tid];
        else           sqj[tid - 128] = g_sq[bj * BN + (tid - 128)];
    }
    __syncthreads();

    // ---- warp-level bf16 GEMM (m16n8k16), warp tile 32x64, 4(m)x2(n) ------
    int wid = tid >> 5, lane = tid & 31;
    int wm = wid & 3, wn = wid >> 2;
    int gq = lane >> 2, q4 = lane & 3;

    float acc[2][8][4];
    #pragma unroll
    for (int mt = 0; mt < 2; mt++)
        #pragma unroll
        for (int nt = 0; nt < 8; nt++)
            #pragma unroll
            for (int r = 0; r < 4; r++) acc[mt][nt][r] = 0.f;

    #pragma unroll
    for (int kc = 0; kc < 4; kc++) {
        int kb = kc * 32 + q4 * 4;             // byte offset of k=2*q4 within chunk
        uint32_t afr[2][4];
        #pragma unroll
        for (int mt = 0; mt < 2; mt++) {
            int row = wm * 32 + mt * 16 + gq;
            const unsigned char* base0 = Asb + row * (SBH * 2) + kb;
            const unsigned char* base1 = Asb + (row + 8) * (SBH * 2) + kb;
            afr[mt][0] = *reinterpret_cast<const uint32_t*>(base0);        // (r,   k0..1)
            afr[mt][1] = *reinterpret_cast<const uint32_t*>(base1);        // (r+8, k0..1)
            afr[mt][2] = *reinterpret_cast<const uint32_t*>(base0 + 16);   // (r,   k8..9)
            afr[mt][3] = *reinterpret_cast<const uint32_t*>(base1 + 16);   // (r+8, k8..9)
        }
        uint32_t bfr[8][2];
        #pragma unroll
        for (int nt = 0; nt < 8; nt++) {
            int col = wn * 64 + nt * 8 + gq;
            const unsigned char* base = Bsb + col * (SBH * 2) + kb;
            bfr[nt][0] = *reinterpret_cast<const uint32_t*>(base);
            bfr[nt][1] = *reinterpret_cast<const uint32_t*>(base + 16);
        }
        #pragma unroll
        for (int mt = 0; mt < 2; mt++)
            #pragma unroll
            for (int nt = 0; nt < 8; nt++)
                mma_bf16(acc[mt][nt], afr[mt], bfr[nt]);
    }

    // ---- epilogue: transform acc in place, direct STG of primary tile ------
    float invl = g_invl;
    #pragma unroll
    for (int mt = 0; mt < 2; mt++) {
        #pragma unroll
        for (int rr = 0; rr < 2; rr++) {
            int rloc = wm * 32 + mt * 16 + gq + rr * 8;
            int grow = bi * BM + rloc;
            float nsqi = -sqi[rloc];
            float* orow = out + (size_t)grow * n + bj * BN;
            #pragma unroll
            for (int nt = 0; nt < 8; nt++) {
                int c0 = wn * 64 + nt * 8 + 2 * q4;
                float2 v;
                v.x = gauss_elem(acc[mt][nt][rr * 2 + 0], sqj[c0],     nsqi, invl);
                v.y = gauss_elem(acc[mt][nt][rr * 2 + 1], sqj[c0 + 1], nsqi, invl);
                acc[mt][nt][rr * 2 + 0] = v.x;     // keep for mirror
                acc[mt][nt][rr * 2 + 1] = v.y;
                *reinterpret_cast<float2*>(orow + c0) = v;
            }
        }
    }

    // ---- mirror tile: transpose through SMEM, coalesced STG ---------------
    if (bi != bj) {
        __syncthreads();   // operand tiles dead -> reuse as staging T
        #pragma unroll
        for (int mt = 0; mt < 2; mt++) {
            #pragma unroll
            for (int rr = 0; rr < 2; rr++) {
                int rloc = wm * 32 + mt * 16 + gq + rr * 8;
                #pragma unroll
                for (int nt = 0; nt < 8; nt++) {
                    int c0 = wn * 64 + nt * 8 + 2 * q4;
                    T[(c0    ) * TSTRIDE + rloc] = acc[mt][nt][rr * 2 + 0];
                    T[(c0 + 1) * TSTRIDE + rloc] = acc[mt][nt][rr * 2 + 1];
                }
            }
        }
        __syncthreads();
        #pragma unroll
        for (int iter = 0; iter < 16; iter++) {
            int r = iter * 8 + wid;
            float4 v = *reinterpret_cast<const float4*>(&T[r * TSTRIDE + 4 * lane]);
            float* orow = out + (size_t)(bj * BN + r) * n + bi * BM + 4 * lane;
            *reinterpret_cast<float4*>(orow) = v;
        }
    }
}

// ------------------------------ launch ---------------------------------------
extern "C" void kernel_launch(void* const* d_in, const int* in_sizes, int n_in,
                              void* d_out, int out_size) {
    const float* X = (const float*)d_in[0];
    int n = in_sizes[0] / DDIM;          // 8192
    float* out = (float*)d_out;

    cudaFuncSetAttribute(gk_main, cudaFuncAttributeMaxDynamicSharedMemorySize,
                         SMEM_BYTES);

    gk_pre<<<64, 1024>>>(X);
    gk_finish<<<1, 1024>>>(n);
    gk_main<<<NTRI, 256, SMEM_BYTES>>>(X, out, n);
}